// round 13
// baseline (speedup 1.0000x reference)
#include <cuda_runtime.h>

#define N_TOKENS 2048   // 8 * 256
#define DIM 128
#define DC 16

__global__ void __launch_bounds__(DIM) flf_quant_k12(
    const float* __restrict__ x,      // [2048, 128]
    const float* __restrict__ W_in,   // [128, 16]
    const float* __restrict__ b_in,   // [16]
    const float* __restrict__ W_out,  // [16, 128]
    const float* __restrict__ b_out,  // [128]
    float* __restrict__ out,          // [2048*128 (+ 2048 indices)]
    int write_indices)
{
    // floats laid out as [warp][e]: offset = warp*16 + e
    __shared__ float2 sm[4][8];

    const int token = blockIdx.x;
    const int t = threadIdx.x;
    const int lane = t & 31;
    const int warp = t >> 5;
    const unsigned FULL = 0xFFFFFFFFu;

    const int ep  = t & 7;           // e-pair: covers e = 2*ep, 2*ep+1
    const int cpl = (t >> 3) & 3;    // 8-dim chunk within the warp's 32 dims
    const int dbase = warp * 32 + cpl * 8;

    // ---- direct x loads: the 8 dims this thread needs (2x LDG.128, L1 broadcast) ----
    const float4* xq = reinterpret_cast<const float4*>(x + (size_t)token * DIM);
    const int qb = dbase >> 2;
    float4 xa = xq[qb], xb = xq[qb + 1];

    // ---- W_in as float2: W_in[d][2ep..2ep+1], d = dbase..dbase+7 ----
    const float2* Wi2 = reinterpret_cast<const float2*>(W_in);
    float2 wi[8];
    #pragma unroll
    for (int i = 0; i < 8; i++) wi[i] = Wi2[(dbase + i) * (DC / 2) + ep];

    // ---- mask-independent W_out / bias prefetch ----
    float wo[DC];
    #pragma unroll
    for (int e = 0; e < DC; e++) wo[e] = W_out[e * DIM + t];
    float bo = b_out[t];
    float bi = b_in[lane & 15];      // pre-barrier, off the critical path

    // ---- z partials: 8 dims x 2 e's = 16 FMAs ----
    float2 p = make_float2(0.f, 0.f);
    p.x = fmaf(xa.x, wi[0].x, p.x); p.y = fmaf(xa.x, wi[0].y, p.y);
    p.x = fmaf(xa.y, wi[1].x, p.x); p.y = fmaf(xa.y, wi[1].y, p.y);
    p.x = fmaf(xa.z, wi[2].x, p.x); p.y = fmaf(xa.z, wi[2].y, p.y);
    p.x = fmaf(xa.w, wi[3].x, p.x); p.y = fmaf(xa.w, wi[3].y, p.y);
    p.x = fmaf(xb.x, wi[4].x, p.x); p.y = fmaf(xb.x, wi[4].y, p.y);
    p.x = fmaf(xb.y, wi[5].x, p.x); p.y = fmaf(xb.y, wi[5].y, p.y);
    p.x = fmaf(xb.z, wi[6].x, p.x); p.y = fmaf(xb.z, wi[6].y, p.y);
    p.x = fmaf(xb.w, wi[7].x, p.x); p.y = fmaf(xb.w, wi[7].y, p.y);

    // ---- wsum precompute (mask-independent): out = 2*sum_set + (bo - sum_all) ----
    float ws01 = (wo[0] + wo[1])   + (wo[2] + wo[3]);
    float ws23 = (wo[4] + wo[5])   + (wo[6] + wo[7]);
    float ws45 = (wo[8] + wo[9])   + (wo[10] + wo[11]);
    float ws67 = (wo[12] + wo[13]) + (wo[14] + wo[15]);
    float base = bo - ((ws01 + ws23) + (ws45 + ws67));

    // ---- warp pre-reduce over the 4 chunks (xor 8, then 16): 4 shfls ----
    p.x += __shfl_xor_sync(FULL, p.x, 8);
    p.y += __shfl_xor_sync(FULL, p.y, 8);
    p.x += __shfl_xor_sync(FULL, p.x, 16);
    p.y += __shfl_xor_sync(FULL, p.y, 16);

    if (lane < 8) sm[warp][ep] = p;
    __syncthreads();

    // ---- final reduce: lane's e = lane&15; smf[w*16 + e], conflict-free broadcast ----
    const float* smf = reinterpret_cast<const float*>(sm);
    const int e = lane & 15;
    float z = ((smf[e] + smf[16 + e]) + (smf[32 + e] + smf[48 + e])) + bi;

    // bit e = (z_e > 0); tie z==0 -> 0 (matches argmin lowest index)
    unsigned mask = __ballot_sync(FULL, z > 0.0f) & 0xFFFFu;

    if (write_indices && t == 0) {
        out[(size_t)N_TOKENS * DIM + token] = (float)(__brev(mask) >> 16);
    }

    // ---- masked sum via predicated adds; two chains ----
    float a = 0.f, c = 0.f;
    #define ACC(E, A) { if (mask & (1u << (E))) A += wo[E]; }
    ACC(0,  a); ACC(1,  c); ACC(2,  a); ACC(3,  c);
    ACC(4,  a); ACC(5,  c); ACC(6,  a); ACC(7,  c);
    ACC(8,  a); ACC(9,  c); ACC(10, a); ACC(11, c);
    ACC(12, a); ACC(13, c); ACC(14, a); ACC(15, c);
    #undef ACC

    out[(size_t)token * DIM + t] = fmaf(2.0f, a + c, base);
}

extern "C" void kernel_launch(void* const* d_in, const int* in_sizes, int n_in,
                              void* d_out, int out_size)
{
    const float* x     = (const float*)d_in[0];
    const float* W_in  = (const float*)d_in[1];
    const float* b_in  = (const float*)d_in[2];
    const float* W_out = (const float*)d_in[3];
    const float* b_out = (const float*)d_in[4];
    float* out = (float*)d_out;

    int write_indices = (out_size >= N_TOKENS * DIM + N_TOKENS) ? 1 : 0;

    flf_quant_k12<<<N_TOKENS, DIM>>>(x, W_in, b_in, W_out, b_out, out, write_indices);
}

// round 16
// speedup vs baseline: 1.0037x; 1.0037x over previous
#include <cuda_runtime.h>

#define N_TOKENS 2048   // 8 * 256
#define DIM 128
#define DC 16
#define TPB 4           // tokens per block
#define GRID_BLOCKS (N_TOKENS / TPB)   // 512

__global__ void __launch_bounds__(DIM) flf_quant_k13(
    const float* __restrict__ x,      // [2048, 128]
    const float* __restrict__ W_in,   // [128, 16]
    const float* __restrict__ b_in,   // [16]
    const float* __restrict__ W_out,  // [16, 128]
    const float* __restrict__ b_out,  // [128]
    float* __restrict__ out,          // [2048*128 (+ 2048 indices)]
    int write_indices)
{
    // floats laid out as [warp][token][e]: offset = warp*64 + tok*16 + e
    __shared__ float2 sm[4][TPB][8];

    const int token0 = blockIdx.x * TPB;
    const int t = threadIdx.x;
    const int lane = t & 31;
    const int warp = t >> 5;
    const unsigned FULL = 0xFFFFFFFFu;

    const int ep  = t & 7;           // e-pair: covers e = 2*ep, 2*ep+1
    const int cpl = (t >> 3) & 3;    // 8-dim chunk within the warp's 32 dims
    const int dbase = warp * 32 + cpl * 8;

    // ---- direct x loads: 8 dims this thread needs, 4 tokens (8x LDG.128, independent) ----
    const float4* xq = reinterpret_cast<const float4*>(x + (size_t)token0 * DIM);
    const int qb = dbase >> 2;
    float4 xa0 = xq[      qb], xb0 = xq[      qb + 1];
    float4 xa1 = xq[32 +  qb], xb1 = xq[32 +  qb + 1];
    float4 xa2 = xq[64 +  qb], xb2 = xq[64 +  qb + 1];
    float4 xa3 = xq[96 +  qb], xb3 = xq[96 +  qb + 1];

    // ---- W_in as float2: W_in[d][2ep..2ep+1], d = dbase..dbase+7 (amortized x4) ----
    const float2* Wi2 = reinterpret_cast<const float2*>(W_in);
    float2 wi[8];
    #pragma unroll
    for (int i = 0; i < 8; i++) wi[i] = Wi2[(dbase + i) * (DC / 2) + ep];

    // ---- mask-independent W_out / bias prefetch (shared by 4 tokens) ----
    float wo[DC];
    #pragma unroll
    for (int e = 0; e < DC; e++) wo[e] = W_out[e * DIM + t];
    float bo = b_out[t];
    float bi = b_in[lane & 15];      // pre-barrier, off the critical path

    // ---- z partials: 8 dims x 2 e x 4 tokens = 64 FMAs, 8 independent chains ----
    float2 p0 = make_float2(0.f, 0.f), p1 = make_float2(0.f, 0.f);
    float2 p2 = make_float2(0.f, 0.f), p3 = make_float2(0.f, 0.f);
    #define STEP(V0, V1, V2, V3, I) \
        p0.x = fmaf((V0), wi[I].x, p0.x); p0.y = fmaf((V0), wi[I].y, p0.y); \
        p1.x = fmaf((V1), wi[I].x, p1.x); p1.y = fmaf((V1), wi[I].y, p1.y); \
        p2.x = fmaf((V2), wi[I].x, p2.x); p2.y = fmaf((V2), wi[I].y, p2.y); \
        p3.x = fmaf((V3), wi[I].x, p3.x); p3.y = fmaf((V3), wi[I].y, p3.y);
    STEP(xa0.x, xa1.x, xa2.x, xa3.x, 0) STEP(xa0.y, xa1.y, xa2.y, xa3.y, 1)
    STEP(xa0.z, xa1.z, xa2.z, xa3.z, 2) STEP(xa0.w, xa1.w, xa2.w, xa3.w, 3)
    STEP(xb0.x, xb1.x, xb2.x, xb3.x, 4) STEP(xb0.y, xb1.y, xb2.y, xb3.y, 5)
    STEP(xb0.z, xb1.z, xb2.z, xb3.z, 6) STEP(xb0.w, xb1.w, xb2.w, xb3.w, 7)
    #undef STEP

    // ---- wsum precompute (mask-independent): out = 2*sum_set + (bo - sum_all) ----
    float ws01 = (wo[0] + wo[1])   + (wo[2] + wo[3]);
    float ws23 = (wo[4] + wo[5])   + (wo[6] + wo[7]);
    float ws45 = (wo[8] + wo[9])   + (wo[10] + wo[11]);
    float ws67 = (wo[12] + wo[13]) + (wo[14] + wo[15]);
    float base = bo - ((ws01 + ws23) + (ws45 + ws67));

    // ---- warp pre-reduce over the 4 chunks (xor 8, then 16): 16 shfls ----
    #define RED(P, OFF) \
        P.x += __shfl_xor_sync(FULL, P.x, OFF); \
        P.y += __shfl_xor_sync(FULL, P.y, OFF);
    RED(p0, 8) RED(p1, 8) RED(p2, 8) RED(p3, 8)
    RED(p0, 16) RED(p1, 16) RED(p2, 16) RED(p3, 16)
    #undef RED

    if (lane < 8) {
        sm[warp][0][ep] = p0;
        sm[warp][1][ep] = p1;
        sm[warp][2][ep] = p2;
        sm[warp][3][ep] = p3;
    }
    __syncthreads();

    // ---- final reduce: lane l covers tokens {l>>4, 2+(l>>4)}, dim l&15 ----
    const float* smf = reinterpret_cast<const float*>(sm);
    float za = ((smf[     lane] + smf[ 64 + lane]) + (smf[128 + lane] + smf[192 + lane])) + bi;
    float zb = ((smf[32 + lane] + smf[ 96 + lane]) + (smf[160 + lane] + smf[224 + lane])) + bi;

    // two ballots give all four masks; bit e = (z_e > 0); tie z==0 -> 0 (argmin lowest idx)
    unsigned bA = __ballot_sync(FULL, za > 0.0f);   // tokens 0 (lo), 1 (hi)
    unsigned bB = __ballot_sync(FULL, zb > 0.0f);   // tokens 2 (lo), 3 (hi)
    unsigned m0 = bA & 0xFFFFu, m1 = bA >> 16;
    unsigned m2 = bB & 0xFFFFu, m3 = bB >> 16;

    if (write_indices && t == 0) {
        float4 idx = make_float4((float)(__brev(m0) >> 16), (float)(__brev(m1) >> 16),
                                 (float)(__brev(m2) >> 16), (float)(__brev(m3) >> 16));
        *reinterpret_cast<float4*>(out + (size_t)N_TOKENS * DIM + token0) = idx;
    }

    // ---- masked sums via predicated adds; two chains per token ----
    float a0 = 0.f, c0 = 0.f, a1 = 0.f, c1 = 0.f;
    float a2 = 0.f, c2 = 0.f, a3 = 0.f, c3 = 0.f;
    #define ACC(E, A0, A1, A2, A3) { \
        if (m0 & (1u << (E))) A0 += wo[E]; \
        if (m1 & (1u << (E))) A1 += wo[E]; \
        if (m2 & (1u << (E))) A2 += wo[E]; \
        if (m3 & (1u << (E))) A3 += wo[E]; }
    ACC(0,  a0, a1, a2, a3); ACC(1,  c0, c1, c2, c3);
    ACC(2,  a0, a1, a2, a3); ACC(3,  c0, c1, c2, c3);
    ACC(4,  a0, a1, a2, a3); ACC(5,  c0, c1, c2, c3);
    ACC(6,  a0, a1, a2, a3); ACC(7,  c0, c1, c2, c3);
    ACC(8,  a0, a1, a2, a3); ACC(9,  c0, c1, c2, c3);
    ACC(10, a0, a1, a2, a3); ACC(11, c0, c1, c2, c3);
    ACC(12, a0, a1, a2, a3); ACC(13, c0, c1, c2, c3);
    ACC(14, a0, a1, a2, a3); ACC(15, c0, c1, c2, c3);
    #undef ACC

    float* op = out + (size_t)token0 * DIM;
    op[          t] = fmaf(2.0f, a0 + c0, base);
    op[    DIM + t] = fmaf(2.0f, a1 + c1, base);
    op[2 * DIM + t] = fmaf(2.0f, a2 + c2, base);
    op[3 * DIM + t] = fmaf(2.0f, a3 + c3, base);
}

extern "C" void kernel_launch(void* const* d_in, const int* in_sizes, int n_in,
                              void* d_out, int out_size)
{
    const float* x     = (const float*)d_in[0];
    const float* W_in  = (const float*)d_in[1];
    const float* b_in  = (const float*)d_in[2];
    const float* W_out = (const float*)d_in[3];
    const float* b_out = (const float*)d_in[4];
    float* out = (float*)d_out;

    int write_indices = (out_size >= N_TOKENS * DIM + N_TOKENS) ? 1 : 0;

    flf_quant_k13<<<GRID_BLOCKS, DIM>>>(x, W_in, b_in, W_out, b_out, out, write_indices);
}

// round 17
// speedup vs baseline: 1.3140x; 1.3092x over previous
#include <cuda_runtime.h>

#define N_TOKENS 2048   // 8 * 256
#define DIM 128
#define DC 16
#define TPB 2           // tokens per block
#define GRID_BLOCKS (N_TOKENS / TPB)   // 1024

__global__ void __launch_bounds__(DIM) flf_quant_k14(
    const float* __restrict__ x,      // [2048, 128]
    const float* __restrict__ W_in,   // [128, 16]
    const float* __restrict__ b_in,   // [16]
    const float* __restrict__ W_out,  // [16, 128]
    const float* __restrict__ b_out,  // [128]
    float* __restrict__ out,          // [2048*128 (+ 2048 indices)]
    int write_indices)
{
    // smem float layout: offset = tok*64 + e*4 + warp  (so [tok*16+e] as float4 = 4 warp partials)
    __shared__ float smf[TPB * DC * 4];

    const int token0 = blockIdx.x * TPB;
    const int t = threadIdx.x;
    const int lane = t & 31;
    const int warp = t >> 5;
    const unsigned FULL = 0xFFFFFFFFu;

    const int ep  = t & 7;           // e-pair: covers e = 2*ep, 2*ep+1
    const int cpl = (t >> 3) & 3;    // 8-dim chunk within the warp's 32 dims
    const int dbase = warp * 32 + cpl * 8;

    // ---- direct x loads: the 8 dims this thread needs, both tokens (4x LDG.128,
    //      8 threads/chunk share addresses -> L1 broadcast) ----
    const float4* xq = reinterpret_cast<const float4*>(x + (size_t)token0 * DIM);
    const int qb = dbase >> 2;
    float4 xa0 = xq[qb],      xb0 = xq[qb + 1];        // token0
    float4 xa1 = xq[32 + qb], xb1 = xq[32 + qb + 1];   // token1

    // ---- W_in as float2: W_in[d][2ep..2ep+1], d = dbase..dbase+7 ----
    const float2* Wi2 = reinterpret_cast<const float2*>(W_in);
    float2 wi[8];
    #pragma unroll
    for (int i = 0; i < 8; i++) wi[i] = Wi2[(dbase + i) * (DC / 2) + ep];

    // ---- mask-independent W_out / bias prefetch (shared by both tokens) ----
    float wo[DC];
    #pragma unroll
    for (int e = 0; e < DC; e++) wo[e] = W_out[e * DIM + t];
    float bo = b_out[t];
    float bi = b_in[lane & 15];      // hoisted pre-barrier

    // ---- z partials: 8 dims x 2 e's x 2 tokens = 32 FMAs ----
    float2 p0 = make_float2(0.f, 0.f), p1 = make_float2(0.f, 0.f);
    #define STEP(XV0, XV1, I) \
        p0.x = fmaf((XV0), wi[I].x, p0.x); p0.y = fmaf((XV0), wi[I].y, p0.y); \
        p1.x = fmaf((XV1), wi[I].x, p1.x); p1.y = fmaf((XV1), wi[I].y, p1.y);
    STEP(xa0.x, xa1.x, 0) STEP(xa0.y, xa1.y, 1)
    STEP(xa0.z, xa1.z, 2) STEP(xa0.w, xa1.w, 3)
    STEP(xb0.x, xb1.x, 4) STEP(xb0.y, xb1.y, 5)
    STEP(xb0.z, xb1.z, 6) STEP(xb0.w, xb1.w, 7)
    #undef STEP

    // ---- wsum precompute (mask-independent): out = 2*sum_set + (bo - sum_all) ----
    float ws01 = (wo[0] + wo[1])   + (wo[2] + wo[3]);
    float ws23 = (wo[4] + wo[5])   + (wo[6] + wo[7]);
    float ws45 = (wo[8] + wo[9])   + (wo[10] + wo[11]);
    float ws67 = (wo[12] + wo[13]) + (wo[14] + wo[15]);
    float base = bo - ((ws01 + ws23) + (ws45 + ws67));

    // ---- warp pre-reduce over the 4 chunks (xor 8, then 16): 8 shfls ----
    p0.x += __shfl_xor_sync(FULL, p0.x, 8);
    p0.y += __shfl_xor_sync(FULL, p0.y, 8);
    p1.x += __shfl_xor_sync(FULL, p1.x, 8);
    p1.y += __shfl_xor_sync(FULL, p1.y, 8);
    p0.x += __shfl_xor_sync(FULL, p0.x, 16);
    p0.y += __shfl_xor_sync(FULL, p0.y, 16);
    p1.x += __shfl_xor_sync(FULL, p1.x, 16);
    p1.y += __shfl_xor_sync(FULL, p1.y, 16);

    // ---- scatter partials: [tok][e][warp] so consumers read one LDS.128 ----
    if (lane < 8) {
        smf[      8 * ep +     warp] = p0.x;   // tok0, e=2ep
        smf[      8 * ep + 4 + warp] = p0.y;   // tok0, e=2ep+1
        smf[64 +  8 * ep +     warp] = p1.x;   // tok1, e=2ep
        smf[64 +  8 * ep + 4 + warp] = p1.y;   // tok1, e=2ep+1
    }
    __syncthreads();

    // ---- post-barrier: lane l -> token l>>4, dim l&15; ONE LDS.128 + 3 adds ----
    float4 f = reinterpret_cast<const float4*>(smf)[lane];
    float z = ((f.x + f.y) + (f.z + f.w)) + bi;

    // one ballot gives both masks; bit e = (z_e > 0); tie z==0 -> 0 (argmin lowest idx)
    unsigned b = __ballot_sync(FULL, z > 0.0f);
    unsigned mask0 = b & 0xFFFFu;
    unsigned mask1 = b >> 16;

    if (write_indices && t == 0) {
        float2 idx = make_float2((float)(__brev(mask0) >> 16),
                                 (float)(__brev(mask1) >> 16));
        *reinterpret_cast<float2*>(out + (size_t)N_TOKENS * DIM + token0) = idx;
    }

    // ---- masked sums via predicated adds; two chains per token ----
    float a0 = 0.f, c0 = 0.f, a1 = 0.f, c1 = 0.f;
    #define ACC(E, A0, A1) { \
        if (mask0 & (1u << (E))) A0 += wo[E]; \
        if (mask1 & (1u << (E))) A1 += wo[E]; }
    ACC(0,  a0, a1); ACC(1,  c0, c1);
    ACC(2,  a0, a1); ACC(3,  c0, c1);
    ACC(4,  a0, a1); ACC(5,  c0, c1);
    ACC(6,  a0, a1); ACC(7,  c0, c1);
    ACC(8,  a0, a1); ACC(9,  c0, c1);
    ACC(10, a0, a1); ACC(11, c0, c1);
    ACC(12, a0, a1); ACC(13, c0, c1);
    ACC(14, a0, a1); ACC(15, c0, c1);
    #undef ACC

    float* op = out + (size_t)token0 * DIM;
    op[t]       = fmaf(2.0f, a0 + c0, base);
    op[DIM + t] = fmaf(2.0f, a1 + c1, base);
}

extern "C" void kernel_launch(void* const* d_in, const int* in_sizes, int n_in,
                              void* d_out, int out_size)
{
    const float* x     = (const float*)d_in[0];
    const float* W_in  = (const float*)d_in[1];
    const float* b_in  = (const float*)d_in[2];
    const float* W_out = (const float*)d_in[3];
    const float* b_out = (const float*)d_in[4];
    float* out = (float*)d_out;

    int write_indices = (out_size >= N_TOKENS * DIM + N_TOKENS) ? 1 : 0;

    flf_quant_k14<<<GRID_BLOCKS, DIM>>>(x, W_in, b_in, W_out, b_out, out, write_indices);
}